// round 1
// baseline (speedup 1.0000x reference)
#include <cuda_runtime.h>
#include <math.h>

// ---------------------------------------------------------------------------
// PolicyLoss: closed-form O(N) decomposition of the 1024x1024x9 pair tensor.
//
// Inputs (metadata order):
//  0 student_logits  f32 [2048,100]
//  1 teacher_logits  f32 [2048,100]
//  2 student_policy  f32 [2048,64]
//  3 teacher_policy  f32 [2048,64]
//  4 W1              f32 [9,128]
//  5 bias1           f32 [9]
//  6 W2              f32 [9,128]
//  7 bias2           f32 [9]
//  8 targets         i32 [2048,1,8]
// Output: scalar f32.
// ---------------------------------------------------------------------------

#define NCLS   100
#define BATCH  2048
#define NPAIR  1024
#define OCH    9

// scratch accumulator layout
#define ACC_CE    0
#define ACC_KL    1
#define ACC_DIFF  2       // 9 channels x {SD, SD2, SE, SE2}  -> 2..37
#define ACC_DIAG  38
#define ACC_SXB   39      // c=1..8 -> 39+(c-1)   sum sB[c]
#define ACC_SXB2  47      // c=2..8 -> 47+(c-2)   sum sB[c]^2
#define ACC_SYA   54      // c=1..8 -> 54+(c-1)   sum sA[c]
#define ACC_SYA2  62      // c=2..8 -> 62+(c-2)   sum sA[c]^2
#define ACC_CNT1  70      // [8][10] even-row target histogram counts
#define ACC_CNT2  150     // [8][10] odd-row target histogram counts
#define ACC_HA    230     // [8][10] sum of sA[c] over even rows with t1==v
#define ACC_HB    310     // [8][10] sum of sB[c] over odd rows with t2==v
#define ACC_TOTAL 512

__device__ float g_acc[ACC_TOTAL];

__device__ __forceinline__ float warp_sum(float v) {
    #pragma unroll
    for (int o = 16; o; o >>= 1) v += __shfl_xor_sync(0xffffffffu, v, o);
    return v;
}

__global__ void init_kernel() {
    g_acc[threadIdx.x] = 0.0f;
}

// -------------------- Kernel 1: CE + KL over the 2048x100 logits ----------
// One warp per row. 4 columns per lane.
__global__ void logits_kernel(const float* __restrict__ slog,
                              const float* __restrict__ tlog,
                              const int*   __restrict__ targets) {
    int warp = threadIdx.x >> 5;
    int lane = threadIdx.x & 31;
    int row  = blockIdx.x * (blockDim.x >> 5) + warp;
    if (row >= BATCH) return;

    const float* s = slog + row * NCLS;
    const float* t = tlog + row * NCLS;

    float sv[4], tv[4];
    #pragma unroll
    for (int j = 0; j < 4; j++) {
        int c = lane + 32 * j;
        sv[j] = (c < NCLS) ? s[c] : -INFINITY;
        tv[j] = (c < NCLS) ? t[c] : -INFINITY;
    }

    // student max
    float m = fmaxf(fmaxf(sv[0], sv[1]), fmaxf(sv[2], sv[3]));
    #pragma unroll
    for (int o = 16; o; o >>= 1) m = fmaxf(m, __shfl_xor_sync(0xffffffffu, m, o));

    float se = 0.f, se4 = 0.f;
    #pragma unroll
    for (int j = 0; j < 4; j++) {
        int c = lane + 32 * j;
        if (c < NCLS) {
            float d = sv[j] - m;
            se  += expf(d);
            se4 += expf(d * 0.25f);
        }
    }
    se  = warp_sum(se);
    se4 = warp_sum(se4);
    float lse  = m + logf(se);                 // log-sum-exp(s)
    float lse4 = m * 0.25f + logf(se4);        // log-sum-exp(s/4)

    // CE: pick s[label]
    int label = targets[row * 8];
    float slabel = 0.f;
    #pragma unroll
    for (int j = 0; j < 4; j++) {
        int c = lane + 32 * j;
        if (c == label) slabel = sv[j];
    }
    slabel = warp_sum(slabel);
    float ce = lse - slabel;                   // -log softmax at label

    // teacher softmax at temperature 4
    float mt = fmaxf(fmaxf(tv[0], tv[1]), fmaxf(tv[2], tv[3])) * 0.25f;
    #pragma unroll
    for (int o = 16; o; o >>= 1) mt = fmaxf(mt, __shfl_xor_sync(0xffffffffu, mt, o));

    float st = 0.f;
    #pragma unroll
    for (int j = 0; j < 4; j++) {
        int c = lane + 32 * j;
        if (c < NCLS) st += expf(tv[j] * 0.25f - mt);
    }
    st = warp_sum(st);
    float logst = logf(st);

    float kl = 0.f;
    #pragma unroll
    for (int j = 0; j < 4; j++) {
        int c = lane + 32 * j;
        if (c < NCLS) {
            float lt  = tv[j] * 0.25f - mt - logst;   // log p_teacher
            float p   = expf(lt);
            float slp = sv[j] * 0.25f - lse4;          // student logp at T=4
            kl += p * (lt - slp);
        }
    }
    kl = warp_sum(kl);

    if (lane == 0) {
        atomicAdd(&g_acc[ACC_CE], ce);
        atomicAdd(&g_acc[ACC_KL], kl);
    }
}

// -------------------- Kernel 2: policy projections + O(N) statistics ------
// 16 blocks x 64 threads = 1024 threads; thread i owns pair index i.
__global__ void policy_kernel(const float* __restrict__ sp,
                              const float* __restrict__ tp,
                              const float* __restrict__ W1,
                              const float* __restrict__ W2,
                              const int*   __restrict__ targets) {
    __shared__ float W1s[OCH * 128];
    __shared__ float W2s[OCH * 128];
    for (int idx = threadIdx.x; idx < OCH * 128; idx += blockDim.x) {
        W1s[idx] = W1[idx];
        W2s[idx] = W2[idx];
    }
    __syncthreads();

    int i    = blockIdx.x * blockDim.x + threadIdx.x;   // 0..1023
    int lane = threadIdx.x & 31;

    float sA[OCH], sB[OCH], tA[OCH], tB[OCH];
    #pragma unroll
    for (int k = 0; k < OCH; k++) { sA[k] = sB[k] = tA[k] = tB[k] = 0.f; }

    const float* spe = sp + (2 * i)     * 64;   // even feat row -> A (index j)
    const float* spo = sp + (2 * i + 1) * 64;   // odd  feat row -> B (index i)
    const float* tpe = tp + (2 * i)     * 64;
    const float* tpo = tp + (2 * i + 1) * 64;

    for (int f = 0; f < 64; f++) {
        float a = spe[f], b = spo[f], c = tpe[f], d = tpo[f];
        #pragma unroll
        for (int k = 0; k < OCH; k++) {
            sA[k] = fmaf(a, W2s[k * 128 + f],      sA[k]);
            sB[k] = fmaf(b, W2s[k * 128 + 64 + f], sB[k]);
            tA[k] = fmaf(c, W1s[k * 128 + f],      tA[k]);
            tB[k] = fmaf(d, W1s[k * 128 + 64 + f], tB[k]);
        }
    }

    // diff statistics per channel (raw, biases folded in at finalize)
    #pragma unroll
    for (int k = 0; k < OCH; k++) {
        float d = sB[k] - tB[k];
        float e = sA[k] - tA[k];
        float r0 = warp_sum(d);
        float r1 = warp_sum(d * d);
        float r2 = warp_sum(e);
        float r3 = warp_sum(e * e);
        if (lane == 0) {
            atomicAdd(&g_acc[ACC_DIFF + 4 * k + 0], r0);
            atomicAdd(&g_acc[ACC_DIFF + 4 * k + 1], r1);
            atomicAdd(&g_acc[ACC_DIFF + 4 * k + 2], r2);
            atomicAdd(&g_acc[ACC_DIFF + 4 * k + 3], r3);
        }
    }

    // diagonal sum (channel 0)
    {
        float r = warp_sum(sB[0] + sA[0]);
        if (lane == 0) atomicAdd(&g_acc[ACC_DIAG], r);
    }

    // student-only sums per channel 1..8 (squares only needed for 2..8)
    #pragma unroll
    for (int c = 1; c < OCH; c++) {
        float rx = warp_sum(sB[c]);
        float ry = warp_sum(sA[c]);
        if (lane == 0) {
            atomicAdd(&g_acc[ACC_SXB + (c - 1)], rx);
            atomicAdd(&g_acc[ACC_SYA + (c - 1)], ry);
        }
        if (c >= 2) {
            float rx2 = warp_sum(sB[c] * sB[c]);
            float ry2 = warp_sum(sA[c] * sA[c]);
            if (lane == 0) {
                atomicAdd(&g_acc[ACC_SXB2 + (c - 2)], rx2);
                atomicAdd(&g_acc[ACC_SYA2 + (c - 2)], ry2);
            }
        }
    }

    // histograms over target values 0..9, per channel c=1..8 (target col c-1)
    const int* t1row = targets + (2 * i)     * 8;   // even targets -> cnt1 / hA
    const int* t2row = targets + (2 * i + 1) * 8;   // odd  targets -> cnt2 / hB
    #pragma unroll
    for (int c = 1; c < OCH; c++) {
        int v1 = t1row[c - 1];
        int v2 = t2row[c - 1];
        int off = (c - 1) * 10;
        atomicAdd(&g_acc[ACC_CNT1 + off + v1], 1.0f);
        atomicAdd(&g_acc[ACC_HA   + off + v1], sA[c]);
        atomicAdd(&g_acc[ACC_CNT2 + off + v2], 1.0f);
        atomicAdd(&g_acc[ACC_HB   + off + v2], sB[c]);
    }
}

// -------------------- Kernel 3: scalar finalize ---------------------------
__global__ void final_kernel(const float* __restrict__ bias1,
                             const float* __restrict__ bias2,
                             float* __restrict__ out) {
    if (threadIdx.x != 0 || blockIdx.x != 0) return;

    const float N = (float)NPAIR;
    const float M = N * N;

    // main-loss pieces
    float ce = g_acc[ACC_CE] / (float)BATCH;
    float kl = 16.0f * g_acc[ACC_KL] / ((float)BATCH * (float)NCLS);

    // policy "kl" part: weighted means of (s - t)^2 over the pair grid
    float klp = 0.f;
    float pgrid = 0.f;
    for (int k = 0; k < OCH; k++) {
        float db  = bias2[k] - bias1[k];
        float SDr = g_acc[ACC_DIFF + 4 * k + 0];
        float SD2 = g_acc[ACC_DIFF + 4 * k + 1];
        float SEr = g_acc[ACC_DIFF + 4 * k + 2];
        float SE2 = g_acc[ACC_DIFF + 4 * k + 3];
        float Sd  = SDr + N * db;
        float Sd2 = SD2 + 2.f * db * SDr + N * db * db;
        float grid = N * Sd2 + N * SE2 + 2.f * Sd * SEr;
        if (k == 0)      klp += grid / M;
        else if (k == 1) klp += 0.5f * grid / M;
        else             pgrid += grid;
    }
    klp += 0.001f * pgrid / (7.f * M);

    // policy "ce" part
    // identity channel: -(sum of diagonal of sI)/M
    float termI = -(g_acc[ACC_DIAG] + N * bias2[0]) / M;

    // class channel (c=1): -0.5/M * sum over matching pairs of sC
    float sm1 = 0.f;
    for (int v = 0; v < 10; v++) {
        float c1 = g_acc[ACC_CNT1 + v];
        float c2 = g_acc[ACC_CNT2 + v];
        float hA = g_acc[ACC_HA + v];
        float hB = g_acc[ACC_HB + v];
        sm1 += c1 * hB + c2 * hA + c1 * c2 * bias2[1];
    }
    float termC = -0.5f * sm1 / M;

    // policy channels (c=2..8): 0.001 * mean((sP - gP)^2), gP = +-1
    float accP = 0.f;
    for (int c = 2; c < OCH; c++) {
        float b    = bias2[c];
        float SxB  = g_acc[ACC_SXB  + (c - 1)];
        float SxB2 = g_acc[ACC_SXB2 + (c - 2)];
        float SyA  = g_acc[ACC_SYA  + (c - 1)];
        float SyA2 = g_acc[ACC_SYA2 + (c - 2)];
        float Sx   = SxB + N * b;
        float Sx2  = SxB2 + 2.f * b * SxB + N * b * b;
        float Sw2  = N * Sx2 + N * SyA2 + 2.f * Sx * SyA;
        float sm = 0.f;
        int off = (c - 1) * 10;
        for (int v = 0; v < 10; v++) {
            float c1 = g_acc[ACC_CNT1 + off + v];
            float c2 = g_acc[ACC_CNT2 + off + v];
            float hA = g_acc[ACC_HA + off + v];
            float hB = g_acc[ACC_HB + off + v];
            sm += c1 * (hB + b * c2) + c2 * hA;
        }
        float Swg = 2.f * sm - N * (Sx + SyA);
        accP += Sw2 - 2.f * Swg + M;           // +M from sum of gP^2 = 1
    }
    float termP = 0.001f * accP / (7.f * M);

    float policy = klp + termI + termC + termP;
    out[0] = ce + kl + policy;
}

// ---------------------------------------------------------------------------
extern "C" void kernel_launch(void* const* d_in, const int* in_sizes, int n_in,
                              void* d_out, int out_size) {
    const float* student_logits = (const float*)d_in[0];
    const float* teacher_logits = (const float*)d_in[1];
    const float* student_policy = (const float*)d_in[2];
    const float* teacher_policy = (const float*)d_in[3];
    const float* W1             = (const float*)d_in[4];
    const float* bias1          = (const float*)d_in[5];
    const float* W2             = (const float*)d_in[6];
    const float* bias2          = (const float*)d_in[7];
    const int*   targets        = (const int*)d_in[8];
    float* out = (float*)d_out;

    init_kernel<<<1, ACC_TOTAL>>>();
    // warp-per-row: 2048 rows, 8 warps/block -> 256 blocks of 256 threads
    logits_kernel<<<BATCH / 8, 256>>>(student_logits, teacher_logits, targets);
    policy_kernel<<<16, 64>>>(student_policy, teacher_policy, W1, W2, targets);
    final_kernel<<<1, 32>>>(bias1, bias2, out);
}

// round 2
// speedup vs baseline: 1.3239x; 1.3239x over previous
#include <cuda_runtime.h>
#include <math.h>

// ---------------------------------------------------------------------------
// PolicyLoss, fully fused single-kernel version.
// Closed-form O(N) decomposition of the 1024x1024x9 pair tensor +
// last-block-done finalize (threadfence reduction pattern).
// ---------------------------------------------------------------------------

#define NCLS   100
#define BATCH  2048
#define NPAIR  1024
#define OCH    9

#define POLICY_BLOCKS 8
#define LOGIT_BLOCKS  128
#define GRID_BLOCKS   (POLICY_BLOCKS + LOGIT_BLOCKS)
#define TPB           256

// policy partial record layout (per policy block), 400 floats
#define P_DIFF  0     // 9 ch x {SD, SD2, SE, SE2}
#define P_DIAG  36
#define P_SXB   37    // c=1..8
#define P_SXB2  45    // c=2..8
#define P_SYA   52    // c=1..8
#define P_SYA2  60    // c=2..8
#define P_CNT1  67    // [8][10]
#define P_CNT2  147   // [8][10]
#define P_HA    227   // [8][10]
#define P_HB    307   // [8][10]
#define P_SIZE  400

__device__ float    g_lp[LOGIT_BLOCKS * 2];
__device__ float    g_pp[POLICY_BLOCKS][P_SIZE];
__device__ unsigned g_ticket = 0;

__device__ __forceinline__ float warp_sum(float v) {
    #pragma unroll
    for (int o = 16; o; o >>= 1) v += __shfl_xor_sync(0xffffffffu, v, o);
    return v;
}

// per-row CE + KL (warp-collective; lane handles cols lane, lane+32, lane+64, lane+96)
__device__ __forceinline__ void row_loss(const float* __restrict__ s,
                                         const float* __restrict__ t,
                                         int label, int lane,
                                         float& ce_out, float& kl_out) {
    float sv[4], tv[4];
    #pragma unroll
    for (int j = 0; j < 4; j++) {
        int c = lane + 32 * j;
        sv[j] = (c < NCLS) ? s[c] : -INFINITY;
        tv[j] = (c < NCLS) ? t[c] : -INFINITY;
    }

    float m = fmaxf(fmaxf(sv[0], sv[1]), fmaxf(sv[2], sv[3]));
    #pragma unroll
    for (int o = 16; o; o >>= 1) m = fmaxf(m, __shfl_xor_sync(0xffffffffu, m, o));

    float se = 0.f, se4 = 0.f, slabel = 0.f;
    #pragma unroll
    for (int j = 0; j < 4; j++) {
        int c = lane + 32 * j;
        if (c < NCLS) {
            float d = sv[j] - m;
            se  += __expf(d);
            se4 += __expf(d * 0.25f);
            if (c == label) slabel = sv[j];
        }
    }
    se     = warp_sum(se);
    se4    = warp_sum(se4);
    slabel = warp_sum(slabel);
    float lse  = m + __logf(se);
    float lse4 = m * 0.25f + __logf(se4);
    ce_out = lse - slabel;

    float mt = fmaxf(fmaxf(tv[0], tv[1]), fmaxf(tv[2], tv[3])) * 0.25f;
    #pragma unroll
    for (int o = 16; o; o >>= 1) mt = fmaxf(mt, __shfl_xor_sync(0xffffffffu, mt, o));

    float st = 0.f;
    #pragma unroll
    for (int j = 0; j < 4; j++) {
        int c = lane + 32 * j;
        if (c < NCLS) st += __expf(tv[j] * 0.25f - mt);
    }
    st = warp_sum(st);
    float logst = __logf(st);

    float kl = 0.f;
    #pragma unroll
    for (int j = 0; j < 4; j++) {
        int c = lane + 32 * j;
        if (c < NCLS) {
            float lt  = tv[j] * 0.25f - mt - logst;  // teacher logp (T=4)
            float p   = __expf(lt);
            float slp = sv[j] * 0.25f - lse4;        // student logp (T=4)
            kl += p * (lt - slp);
        }
    }
    kl_out = warp_sum(kl);
}

__global__ void __launch_bounds__(TPB)
fused_kernel(const float* __restrict__ slog,
             const float* __restrict__ tlog,
             const float* __restrict__ sp,
             const float* __restrict__ tp,
             const float* __restrict__ W1,
             const float* __restrict__ bias1,
             const float* __restrict__ W2,
             const float* __restrict__ bias2,
             const int*   __restrict__ targets,
             float* __restrict__ out) {
    __shared__ __align__(16) float sW[2 * OCH * 128];   // W2 | W1
    __shared__ float sAcc[P_SIZE];
    __shared__ float sRed[24];
    __shared__ float b1s[OCH], b2s[OCH];
    __shared__ unsigned is_last;

    const int tid  = threadIdx.x;
    const int lane = tid & 31;
    const int warp = tid >> 5;
    const int bid  = blockIdx.x;

    if (bid < POLICY_BLOCKS) {
        // ----------------- policy projections + O(N) statistics -----------
        for (int idx = tid; idx < OCH * 128; idx += TPB) {
            sW[idx]             = W2[idx];
            sW[OCH * 128 + idx] = W1[idx];
        }
        for (int idx = tid; idx < P_SIZE; idx += TPB) sAcc[idx] = 0.f;
        __syncthreads();

        // 2 threads per pair: half h = lane>>4 covers features [32h, 32h+32)
        const int h = lane >> 4;
        const int i = bid * 128 + warp * 16 + (lane & 15);   // pair 0..1023
        const int fbase = h * 32;

        const float4* spA = (const float4*)(sp + (2 * i)     * 64 + fbase);
        const float4* spB = (const float4*)(sp + (2 * i + 1) * 64 + fbase);
        const float4* tpA = (const float4*)(tp + (2 * i)     * 64 + fbase);
        const float4* tpB = (const float4*)(tp + (2 * i + 1) * 64 + fbase);

        float sA[OCH], sB[OCH], tA[OCH], tB[OCH];
        #pragma unroll
        for (int k = 0; k < OCH; k++) { sA[k] = sB[k] = tA[k] = tB[k] = 0.f; }

        #pragma unroll
        for (int q = 0; q < 8; q++) {
            float4 a = spA[q], b = spB[q], c = tpA[q], d = tpB[q];
            int f = fbase + 4 * q;
            #pragma unroll
            for (int k = 0; k < OCH; k++) {
                float4 w2a = *(const float4*)&sW[k * 128 + f];
                float4 w2b = *(const float4*)&sW[k * 128 + 64 + f];
                float4 w1a = *(const float4*)&sW[OCH * 128 + k * 128 + f];
                float4 w1b = *(const float4*)&sW[OCH * 128 + k * 128 + 64 + f];
                sA[k] += a.x*w2a.x + a.y*w2a.y + a.z*w2a.z + a.w*w2a.w;
                sB[k] += b.x*w2b.x + b.y*w2b.y + b.z*w2b.z + b.w*w2b.w;
                tA[k] += c.x*w1a.x + c.y*w1a.y + c.z*w1a.z + c.w*w1a.w;
                tB[k] += d.x*w1b.x + d.y*w1b.y + d.z*w1b.z + d.w*w1b.w;
            }
        }
        // combine the two feature halves (partner lane = lane ^ 16)
        #pragma unroll
        for (int k = 0; k < OCH; k++) {
            sA[k] += __shfl_xor_sync(0xffffffffu, sA[k], 16);
            sB[k] += __shfl_xor_sync(0xffffffffu, sB[k], 16);
            tA[k] += __shfl_xor_sync(0xffffffffu, tA[k], 16);
            tB[k] += __shfl_xor_sync(0xffffffffu, tB[k], 16);
        }
        // only h==0 half contributes to statistics (16 pairs per warp)
        if (h) {
            #pragma unroll
            for (int k = 0; k < OCH; k++) { sA[k] = sB[k] = tA[k] = tB[k] = 0.f; }
        }

        #pragma unroll
        for (int k = 0; k < OCH; k++) {
            float d = sB[k] - tB[k];
            float e = sA[k] - tA[k];
            float r0 = warp_sum(d);
            float r1 = warp_sum(d * d);
            float r2 = warp_sum(e);
            float r3 = warp_sum(e * e);
            if (lane == 0) {
                atomicAdd(&sAcc[P_DIFF + 4 * k + 0], r0);
                atomicAdd(&sAcc[P_DIFF + 4 * k + 1], r1);
                atomicAdd(&sAcc[P_DIFF + 4 * k + 2], r2);
                atomicAdd(&sAcc[P_DIFF + 4 * k + 3], r3);
            }
        }
        {
            float r = warp_sum(sB[0] + sA[0]);
            if (lane == 0) atomicAdd(&sAcc[P_DIAG], r);
        }
        #pragma unroll
        for (int c = 1; c < OCH; c++) {
            float rx = warp_sum(sB[c]);
            float ry = warp_sum(sA[c]);
            if (lane == 0) {
                atomicAdd(&sAcc[P_SXB + (c - 1)], rx);
                atomicAdd(&sAcc[P_SYA + (c - 1)], ry);
            }
            if (c >= 2) {
                float rx2 = warp_sum(sB[c] * sB[c]);
                float ry2 = warp_sum(sA[c] * sA[c]);
                if (lane == 0) {
                    atomicAdd(&sAcc[P_SXB2 + (c - 2)], rx2);
                    atomicAdd(&sAcc[P_SYA2 + (c - 2)], ry2);
                }
            }
        }

        // target histograms (h==0 threads own valid full sums)
        if (h == 0) {
            const int* t1 = targets + (2 * i)     * 8;
            const int* t2 = targets + (2 * i + 1) * 8;
            #pragma unroll
            for (int c = 1; c < OCH; c++) {
                int v1 = t1[c - 1];
                int v2 = t2[c - 1];
                int off = (c - 1) * 10;
                atomicAdd(&sAcc[P_CNT1 + off + v1], 1.0f);
                atomicAdd(&sAcc[P_HA   + off + v1], sA[c]);
                atomicAdd(&sAcc[P_CNT2 + off + v2], 1.0f);
                atomicAdd(&sAcc[P_HB   + off + v2], sB[c]);
            }
        }
        __syncthreads();
        for (int idx = tid; idx < P_SIZE; idx += TPB) g_pp[bid][idx] = sAcc[idx];
    } else {
        // ----------------- logits CE + KL: 2 rows per warp -----------------
        const int lb = bid - POLICY_BLOCKS;           // 0..127
        float ce = 0.f, kl = 0.f;
        #pragma unroll
        for (int r = 0; r < 2; r++) {
            int row = lb * 16 + warp * 2 + r;
            float c1, k1;
            row_loss(slog + row * NCLS, tlog + row * NCLS,
                     targets[row * 8], lane, c1, k1);
            ce += c1; kl += k1;
        }
        if (lane == 0) { sRed[warp] = ce; sRed[8 + warp] = kl; }
        __syncthreads();
        if (tid == 0) {
            float tc = 0.f, tk = 0.f;
            #pragma unroll
            for (int w = 0; w < 8; w++) { tc += sRed[w]; tk += sRed[8 + w]; }
            g_lp[lb * 2]     = tc;
            g_lp[lb * 2 + 1] = tk;
        }
    }

    // ----------------- last-block-done finalize ---------------------------
    __threadfence();
    if (tid == 0) {
        unsigned t = atomicAdd(&g_ticket, 1u);
        is_last = (t == GRID_BLOCKS - 1) ? 1u : 0u;
    }
    __syncthreads();
    if (!is_last) return;
    if (tid == 0) g_ticket = 0;   // reset for next graph replay

    // parallel gather of partials (all in L2 now)
    if (tid < OCH) { b1s[tid] = bias1[tid]; b2s[tid] = bias2[tid]; }

    float vce = 0.f, vkl = 0.f;
    if (tid < LOGIT_BLOCKS) { vce = g_lp[tid * 2]; vkl = g_lp[tid * 2 + 1]; }
    vce = warp_sum(vce);
    vkl = warp_sum(vkl);
    if (lane == 0) { sRed[warp] = vce; sRed[8 + warp] = vkl; }

    for (int idx = tid; idx < P_SIZE; idx += TPB) {
        float s = 0.f;
        #pragma unroll
        for (int p = 0; p < POLICY_BLOCKS; p++) s += g_pp[p][idx];
        sAcc[idx] = s;
    }
    __syncthreads();

    if (tid == 0) {
        float ce_sum = 0.f, kl_sum = 0.f;
        #pragma unroll
        for (int w = 0; w < 8; w++) { ce_sum += sRed[w]; kl_sum += sRed[8 + w]; }

        const float N = (float)NPAIR;
        const float M = N * N;

        float ce = ce_sum / (float)BATCH;
        float kl = 16.0f * kl_sum / ((float)BATCH * (float)NCLS);

        // policy "kl": weighted means of (s - t)^2 over the pair grid
        float klp = 0.f, pgrid = 0.f;
        for (int k = 0; k < OCH; k++) {
            float db  = b2s[k] - b1s[k];
            float SDr = sAcc[P_DIFF + 4 * k + 0];
            float SD2 = sAcc[P_DIFF + 4 * k + 1];
            float SEr = sAcc[P_DIFF + 4 * k + 2];
            float SE2 = sAcc[P_DIFF + 4 * k + 3];
            float Sd  = SDr + N * db;
            float Sd2 = SD2 + 2.f * db * SDr + N * db * db;
            float grid = N * Sd2 + N * SE2 + 2.f * Sd * SEr;
            if (k == 0)      klp += grid / M;
            else if (k == 1) klp += 0.5f * grid / M;
            else             pgrid += grid;
        }
        klp += 0.001f * pgrid / (7.f * M);

        // policy "ce": identity channel diagonal
        float termI = -(sAcc[P_DIAG] + N * b2s[0]) / M;

        // class channel (c=1): matching-pair sum via histograms
        float sm1 = 0.f;
        for (int v = 0; v < 10; v++) {
            float c1 = sAcc[P_CNT1 + v];
            float c2 = sAcc[P_CNT2 + v];
            float hA = sAcc[P_HA + v];
            float hB = sAcc[P_HB + v];
            sm1 += c1 * hB + c2 * hA + c1 * c2 * b2s[1];
        }
        float termC = -0.5f * sm1 / M;

        // policy channels c=2..8: 0.001 * mean((sP - gP)^2), gP = +-1
        float accP = 0.f;
        for (int c = 2; c < OCH; c++) {
            float b    = b2s[c];
            float SxB  = sAcc[P_SXB  + (c - 1)];
            float SxB2 = sAcc[P_SXB2 + (c - 2)];
            float SyA  = sAcc[P_SYA  + (c - 1)];
            float SyA2 = sAcc[P_SYA2 + (c - 2)];
            float Sx   = SxB + N * b;
            float Sx2  = SxB2 + 2.f * b * SxB + N * b * b;
            float Sw2  = N * Sx2 + N * SyA2 + 2.f * Sx * SyA;
            float sm = 0.f;
            int off = (c - 1) * 10;
            for (int v = 0; v < 10; v++) {
                float c1 = sAcc[P_CNT1 + off + v];
                float c2 = sAcc[P_CNT2 + off + v];
                float hA = sAcc[P_HA + off + v];
                float hB = sAcc[P_HB + off + v];
                sm += c1 * (hB + b * c2) + c2 * hA;
            }
            float Swg = 2.f * sm - N * (Sx + SyA);
            accP += Sw2 - 2.f * Swg + M;
        }
        float termP = 0.001f * accP / (7.f * M);

        out[0] = ce + kl + klp + termI + termC + termP;
    }
}

// ---------------------------------------------------------------------------
extern "C" void kernel_launch(void* const* d_in, const int* in_sizes, int n_in,
                              void* d_out, int out_size) {
    const float* student_logits = (const float*)d_in[0];
    const float* teacher_logits = (const float*)d_in[1];
    const float* student_policy = (const float*)d_in[2];
    const float* teacher_policy = (const float*)d_in[3];
    const float* W1             = (const float*)d_in[4];
    const float* bias1          = (const float*)d_in[5];
    const float* W2             = (const float*)d_in[6];
    const float* bias2          = (const float*)d_in[7];
    const int*   targets        = (const int*)d_in[8];
    float* out = (float*)d_out;

    fused_kernel<<<GRID_BLOCKS, TPB>>>(student_logits, teacher_logits,
                                       student_policy, teacher_policy,
                                       W1, bias1, W2, bias2, targets, out);
}

// round 3
// speedup vs baseline: 1.9061x; 1.4397x over previous
#include <cuda_runtime.h>
#include <math.h>

// ---------------------------------------------------------------------------
// PolicyLoss fused single kernel, v3.
//  - 256 logits blocks (warp-per-row), 16 policy blocks (4 threads/pair)
//  - stats via per-warp shared slices (no atomics), hist via low-contention
//    shared atomics, last-block-done finalize.
// ---------------------------------------------------------------------------

#define NCLS   100
#define BATCH  2048
#define NPAIR  1024
#define OCH    9

#define POLICY_BLOCKS 16
#define LOGIT_BLOCKS  256
#define GRID_BLOCKS   (POLICY_BLOCKS + LOGIT_BLOCKS)
#define TPB           256

// policy partial record layout (per policy block)
#define F_DIFF  0     // 9 ch x {SD, SD2, SE, SE2} -> 0..35
#define F_DIAG  36
#define F_SXB   37    // c=1..8 -> 37+(c-1)
#define F_SXB2  45    // c=2..8 -> 45+(c-2)
#define F_SYA   52    // c=1..8
#define F_SYA2  60    // c=2..8
#define F_NSTAT 67
#define F_CNT1  67    // [8][10]
#define F_CNT2  147
#define F_HA    227
#define F_HB    307
#define F_SIZE  387

__device__ float    g_lp[LOGIT_BLOCKS * 2];
__device__ float    g_pp[POLICY_BLOCKS][F_SIZE];
__device__ unsigned g_ticket = 0;

__device__ __forceinline__ float warp_sum(float v) {
    #pragma unroll
    for (int o = 16; o; o >>= 1) v += __shfl_xor_sync(0xffffffffu, v, o);
    return v;
}

// per-row CE + KL (warp-collective)
__device__ __forceinline__ void row_loss(const float* __restrict__ s,
                                         const float* __restrict__ t,
                                         int label, int lane,
                                         float& ce_out, float& kl_out) {
    float sv[4], tv[4];
    #pragma unroll
    for (int j = 0; j < 4; j++) {
        int c = lane + 32 * j;
        sv[j] = (c < NCLS) ? s[c] : -INFINITY;
        tv[j] = (c < NCLS) ? t[c] : -INFINITY;
    }

    float m = fmaxf(fmaxf(sv[0], sv[1]), fmaxf(sv[2], sv[3]));
    #pragma unroll
    for (int o = 16; o; o >>= 1) m = fmaxf(m, __shfl_xor_sync(0xffffffffu, m, o));

    float se = 0.f, se4 = 0.f, slabel = 0.f;
    #pragma unroll
    for (int j = 0; j < 4; j++) {
        int c = lane + 32 * j;
        if (c < NCLS) {
            float d = sv[j] - m;
            se  += __expf(d);
            se4 += __expf(d * 0.25f);
            if (c == label) slabel = sv[j];
        }
    }
    se     = warp_sum(se);
    se4    = warp_sum(se4);
    slabel = warp_sum(slabel);
    float lse  = m + __logf(se);
    float lse4 = m * 0.25f + __logf(se4);
    ce_out = lse - slabel;

    float mt = fmaxf(fmaxf(tv[0], tv[1]), fmaxf(tv[2], tv[3])) * 0.25f;
    #pragma unroll
    for (int o = 16; o; o >>= 1) mt = fmaxf(mt, __shfl_xor_sync(0xffffffffu, mt, o));

    float st = 0.f;
    #pragma unroll
    for (int j = 0; j < 4; j++) {
        int c = lane + 32 * j;
        if (c < NCLS) st += __expf(tv[j] * 0.25f - mt);
    }
    st = warp_sum(st);
    float logst = __logf(st);

    float kl = 0.f;
    #pragma unroll
    for (int j = 0; j < 4; j++) {
        int c = lane + 32 * j;
        if (c < NCLS) {
            float lt  = tv[j] * 0.25f - mt - logst;  // teacher logp (T=4)
            float p   = __expf(lt);
            float slp = sv[j] * 0.25f - lse4;        // student logp (T=4)
            kl += p * (lt - slp);
        }
    }
    kl_out = warp_sum(kl);
}

__global__ void __launch_bounds__(TPB)
fused_kernel(const float* __restrict__ slog,
             const float* __restrict__ tlog,
             const float* __restrict__ sp,
             const float* __restrict__ tp,
             const float* __restrict__ W1,
             const float* __restrict__ bias1,
             const float* __restrict__ W2,
             const float* __restrict__ bias2,
             const int*   __restrict__ targets,
             float* __restrict__ out) {
    __shared__ __align__(16) float sW[2 * OCH * 128];   // W2 | W1  (policy only)
    __shared__ float sStat[8 * F_NSTAT];                // per-warp stat slices
    __shared__ float sHist[320];                        // cnt1|cnt2|hA|hB
    __shared__ float sAcc[F_SIZE];                      // finalize scratch
    __shared__ float sRed[24];
    __shared__ float b1s[OCH], b2s[OCH];
    __shared__ unsigned is_last;

    const int tid  = threadIdx.x;
    const int lane = tid & 31;
    const int warp = tid >> 5;
    const int bid  = blockIdx.x;

    if (bid < POLICY_BLOCKS) {
        // ----------------- policy: 4 threads per pair ----------------------
        for (int idx = tid; idx < OCH * 128; idx += TPB) {
            sW[idx]             = W2[idx];
            sW[OCH * 128 + idx] = W1[idx];
        }
        for (int idx = tid; idx < 320; idx += TPB) sHist[idx] = 0.f;
        __syncthreads();

        const int q = lane >> 3;                         // feature quarter
        const int i = bid * 64 + warp * 8 + (lane & 7);  // pair 0..1023
        const int fbase = q * 16;

        const float4* spA = (const float4*)(sp + (2 * i)     * 64 + fbase);
        const float4* spB = (const float4*)(sp + (2 * i + 1) * 64 + fbase);
        const float4* tpA = (const float4*)(tp + (2 * i)     * 64 + fbase);
        const float4* tpB = (const float4*)(tp + (2 * i + 1) * 64 + fbase);

        float sA[OCH], sB[OCH], tA[OCH], tB[OCH];
        #pragma unroll
        for (int k = 0; k < OCH; k++) { sA[k] = sB[k] = tA[k] = tB[k] = 0.f; }

        #pragma unroll
        for (int v = 0; v < 4; v++) {
            float4 a = spA[v], b = spB[v], c = tpA[v], d = tpB[v];
            int f = fbase + 4 * v;
            #pragma unroll
            for (int k = 0; k < OCH; k++) {
                float4 w2a = *(const float4*)&sW[k * 128 + f];
                float4 w2b = *(const float4*)&sW[k * 128 + 64 + f];
                float4 w1a = *(const float4*)&sW[OCH * 128 + k * 128 + f];
                float4 w1b = *(const float4*)&sW[OCH * 128 + k * 128 + 64 + f];
                sA[k] += a.x*w2a.x + a.y*w2a.y + a.z*w2a.z + a.w*w2a.w;
                sB[k] += b.x*w2b.x + b.y*w2b.y + b.z*w2b.z + b.w*w2b.w;
                tA[k] += c.x*w1a.x + c.y*w1a.y + c.z*w1a.z + c.w*w1a.w;
                tB[k] += d.x*w1b.x + d.y*w1b.y + d.z*w1b.z + d.w*w1b.w;
            }
        }
        // combine quarters: after xor 8 and xor 16, ALL lanes hold full sums
        #pragma unroll
        for (int k = 0; k < OCH; k++) {
            sA[k] += __shfl_xor_sync(0xffffffffu, sA[k], 8);
            sB[k] += __shfl_xor_sync(0xffffffffu, sB[k], 8);
            tA[k] += __shfl_xor_sync(0xffffffffu, tA[k], 8);
            tB[k] += __shfl_xor_sync(0xffffffffu, tB[k], 8);
            sA[k] += __shfl_xor_sync(0xffffffffu, sA[k], 16);
            sB[k] += __shfl_xor_sync(0xffffffffu, sB[k], 16);
            tA[k] += __shfl_xor_sync(0xffffffffu, tA[k], 16);
            tB[k] += __shfl_xor_sync(0xffffffffu, tB[k], 16);
        }

        // warp-sum over 32 lanes counts each pair 4x -> scale by 0.25 (exact)
        #define WST(j, val) { float r_ = warp_sum(val); \
                              if (lane == 0) sStat[warp * F_NSTAT + (j)] = r_ * 0.25f; }
        #pragma unroll
        for (int k = 0; k < OCH; k++) {
            float d = sB[k] - tB[k];
            float e = sA[k] - tA[k];
            WST(F_DIFF + 4 * k + 0, d);
            WST(F_DIFF + 4 * k + 1, d * d);
            WST(F_DIFF + 4 * k + 2, e);
            WST(F_DIFF + 4 * k + 3, e * e);
        }
        WST(F_DIAG, sB[0] + sA[0]);
        #pragma unroll
        for (int c = 1; c < OCH; c++) {
            WST(F_SXB + (c - 1), sB[c]);
            WST(F_SYA + (c - 1), sA[c]);
            if (c >= 2) {
                WST(F_SXB2 + (c - 2), sB[c] * sB[c]);
                WST(F_SYA2 + (c - 2), sA[c] * sA[c]);
            }
        }
        #undef WST

        // histograms: only q==0 lanes (8 per warp) contribute
        if (q == 0) {
            const int* t1 = targets + (2 * i)     * 8;
            const int* t2 = targets + (2 * i + 1) * 8;
            #pragma unroll
            for (int c = 1; c < OCH; c++) {
                int v1 = t1[c - 1];
                int v2 = t2[c - 1];
                int off = (c - 1) * 10;
                atomicAdd(&sHist[off + v1],       1.0f);     // cnt1
                atomicAdd(&sHist[160 + off + v1], sA[c]);    // hA
                atomicAdd(&sHist[80 + off + v2],  1.0f);     // cnt2
                atomicAdd(&sHist[240 + off + v2], sB[c]);    // hB
            }
        }
        __syncthreads();

        // block combine: stats (sum 8 warps) + hist copy -> global partials
        for (int j = tid; j < F_NSTAT; j += TPB) {
            float s = 0.f;
            #pragma unroll
            for (int w = 0; w < 8; w++) s += sStat[w * F_NSTAT + j];
            g_pp[bid][j] = s;
        }
        for (int j = tid; j < 320; j += TPB) g_pp[bid][F_NSTAT + j] = sHist[j];
    } else {
        // ----------------- logits CE + KL: 1 row per warp -------------------
        const int lb  = bid - POLICY_BLOCKS;          // 0..255
        const int row = lb * 8 + warp;
        float ce, kl;
        row_loss(slog + row * NCLS, tlog + row * NCLS,
                 targets[row * 8], lane, ce, kl);
        if (lane == 0) { sRed[warp] = ce; sRed[8 + warp] = kl; }
        __syncthreads();
        if (tid == 0) {
            float tc = 0.f, tk = 0.f;
            #pragma unroll
            for (int w = 0; w < 8; w++) { tc += sRed[w]; tk += sRed[8 + w]; }
            g_lp[lb * 2]     = tc;
            g_lp[lb * 2 + 1] = tk;
        }
    }

    // ----------------- last-block-done finalize ---------------------------
    __threadfence();
    if (tid == 0) {
        unsigned t = atomicAdd(&g_ticket, 1u);
        is_last = (t == GRID_BLOCKS - 1) ? 1u : 0u;
    }
    __syncthreads();
    if (!is_last) return;
    if (tid == 0) g_ticket = 0;   // reset for next graph replay
    __threadfence();

    if (tid < OCH) { b1s[tid] = bias1[tid]; b2s[tid] = bias2[tid]; }

    // gather logits partials (256 pairs)
    float vce = g_lp[tid * 2];
    float vkl = g_lp[tid * 2 + 1];
    vce = warp_sum(vce);
    vkl = warp_sum(vkl);
    if (lane == 0) { sRed[warp] = vce; sRed[8 + warp] = vkl; }

    // gather policy partials
    for (int idx = tid; idx < F_SIZE; idx += TPB) {
        float s = 0.f;
        #pragma unroll
        for (int p = 0; p < POLICY_BLOCKS; p++) s += g_pp[p][idx];
        sAcc[idx] = s;
    }
    __syncthreads();

    if (tid == 0) {
        float ce_sum = 0.f, kl_sum = 0.f;
        #pragma unroll
        for (int w = 0; w < 8; w++) { ce_sum += sRed[w]; kl_sum += sRed[8 + w]; }

        const float N = (float)NPAIR;
        const float M = N * N;

        float ce = ce_sum / (float)BATCH;
        float kl = 16.0f * kl_sum / ((float)BATCH * (float)NCLS);

        // policy "kl": weighted means of (s - t)^2 over the pair grid
        float klp = 0.f, pgrid = 0.f;
        for (int k = 0; k < OCH; k++) {
            float db  = b2s[k] - b1s[k];
            float SDr = sAcc[F_DIFF + 4 * k + 0];
            float SD2 = sAcc[F_DIFF + 4 * k + 1];
            float SEr = sAcc[F_DIFF + 4 * k + 2];
            float SE2 = sAcc[F_DIFF + 4 * k + 3];
            float Sd  = SDr + N * db;
            float Sd2 = SD2 + 2.f * db * SDr + N * db * db;
            float grid = N * Sd2 + N * SE2 + 2.f * Sd * SEr;
            if (k == 0)      klp += grid / M;
            else if (k == 1) klp += 0.5f * grid / M;
            else             pgrid += grid;
        }
        klp += 0.001f * pgrid / (7.f * M);

        // policy "ce": identity channel diagonal
        float termI = -(sAcc[F_DIAG] + N * b2s[0]) / M;

        // class channel (c=1): matching-pair sum via histograms
        float sm1 = 0.f;
        for (int v = 0; v < 10; v++) {
            float c1 = sAcc[F_CNT1 + v];
            float c2 = sAcc[F_CNT2 + v];
            float hA = sAcc[F_HA + v];
            float hB = sAcc[F_HB + v];
            sm1 += c1 * hB + c2 * hA + c1 * c2 * b2s[1];
        }
        float termC = -0.5f * sm1 / M;

        // policy channels c=2..8: 0.001 * mean((sP - gP)^2), gP = +-1
        float accP = 0.f;
        for (int c = 2; c < OCH; c++) {
            float b    = b2s[c];
            float SxB  = sAcc[F_SXB  + (c - 1)];
            float SxB2 = sAcc[F_SXB2 + (c - 2)];
            float SyA  = sAcc[F_SYA  + (c - 1)];
            float SyA2 = sAcc[F_SYA2 + (c - 2)];
            float Sx   = SxB + N * b;
            float Sx2  = SxB2 + 2.f * b * SxB + N * b * b;
            float Sw2  = N * Sx2 + N * SyA2 + 2.f * Sx * SyA;
            float sm = 0.f;
            int off = (c - 1) * 10;
            for (int v = 0; v < 10; v++) {
                float c1 = sAcc[F_CNT1 + off + v];
                float c2 = sAcc[F_CNT2 + off + v];
                float hA = sAcc[F_HA + off + v];
                float hB = sAcc[F_HB + off + v];
                sm += c1 * (hB + b * c2) + c2 * hA;
            }
            float Swg = 2.f * sm - N * (Sx + SyA);
            accP += Sw2 - 2.f * Swg + M;
        }
        float termP = 0.001f * accP / (7.f * M);

        out[0] = ce + kl + klp + termI + termC + termP;
    }
}

// ---------------------------------------------------------------------------
extern "C" void kernel_launch(void* const* d_in, const int* in_sizes, int n_in,
                              void* d_out, int out_size) {
    const float* student_logits = (const float*)d_in[0];
    const float* teacher_logits = (const float*)d_in[1];
    const float* student_policy = (const float*)d_in[2];
    const float* teacher_policy = (const float*)d_in[3];
    const float* W1             = (const float*)d_in[4];
    const float* bias1          = (const float*)d_in[5];
    const float* W2             = (const float*)d_in[6];
    const float* bias2          = (const float*)d_in[7];
    const int*   targets        = (const int*)d_in[8];
    float* out = (float*)d_out;

    fused_kernel<<<GRID_BLOCKS, TPB>>>(student_logits, teacher_logits,
                                       student_policy, teacher_policy,
                                       W1, bias1, W2, bias2, targets, out);
}

// round 5
// speedup vs baseline: 3.0526x; 1.6015x over previous
#include <cuda_runtime.h>
#include <math.h>

// ---------------------------------------------------------------------------
// PolicyLoss fused single kernel, v5.
//  - 256 logits blocks (warp-per-row, no-max softmax, shfl reductions)
//  - 32 policy blocks (8 threads/pair), 2-shfl stat reductions,
//    channel-split histograms
//  - last-block-done finalize
// ---------------------------------------------------------------------------

#define NCLS   100
#define BATCH  2048
#define NPAIR  1024
#define OCH    9

#define POLICY_BLOCKS 32
#define LOGIT_BLOCKS  256
#define GRID_BLOCKS   (POLICY_BLOCKS + LOGIT_BLOCKS)
#define TPB           256

// policy partial record layout (per policy block)
#define F_DIFF  0     // 9 ch x {SD, SD2, SE, SE2} -> 0..35
#define F_DIAG  36
#define F_SXB   37    // c=1..8 -> 37+(c-1)
#define F_SXB2  45    // c=2..8 -> 45+(c-2)
#define F_SYA   52    // c=1..8
#define F_SYA2  60    // c=2..8
#define F_NSTAT 67
#define F_CNT1  67    // [8][10]
#define F_CNT2  147
#define F_HA    227
#define F_HB    307
#define F_SIZE  387

__device__ float    g_lp[LOGIT_BLOCKS * 2];
__device__ float    g_pp[POLICY_BLOCKS][F_SIZE];
__device__ unsigned g_ticket = 0;

__device__ __forceinline__ float warp_sum(float v) {
    #pragma unroll
    for (int o = 16; o; o >>= 1) v += __shfl_xor_sync(0xffffffffu, v, o);
    return v;
}

// sum over the 4 distinct values held (8x-replicated) in lane groups of 4
__device__ __forceinline__ float quad_sum(float v) {
    v += __shfl_xor_sync(0xffffffffu, v, 1);
    v += __shfl_xor_sync(0xffffffffu, v, 2);
    return v;
}

__global__ void __launch_bounds__(TPB)
fused_kernel(const float* __restrict__ slog,
             const float* __restrict__ tlog,
             const float* __restrict__ sp,
             const float* __restrict__ tp,
             const float* __restrict__ W1,
             const float* __restrict__ bias1,
             const float* __restrict__ W2,
             const float* __restrict__ bias2,
             const int*   __restrict__ targets,
             float* __restrict__ out) {
    __shared__ __align__(16) float sW[2 * OCH * 128];   // W2 | W1 (policy only)
    __shared__ float sStat[8 * F_NSTAT];                // per-warp stat slices
    __shared__ float sHist[320];                        // cnt1|cnt2|hA|hB
    __shared__ float sAcc[F_SIZE];                      // finalize scratch
    __shared__ float sRed[16];
    __shared__ float b1s[OCH], b2s[OCH];
    __shared__ unsigned is_last;

    const int tid  = threadIdx.x;
    const int lane = tid & 31;
    const int warp = tid >> 5;
    const int bid  = blockIdx.x;

    if (bid < POLICY_BLOCKS) {
        // ----------------- policy: 8 threads per pair ----------------------
        {   // stage W2|W1 into smem with float4
            const float4* w2v = (const float4*)W2;
            const float4* w1v = (const float4*)W1;
            float4* d = (float4*)sW;
            for (int idx = tid; idx < (OCH * 128) / 4; idx += TPB) {
                d[idx]                   = w2v[idx];
                d[(OCH * 128) / 4 + idx] = w1v[idx];
            }
        }
        for (int idx = tid; idx < 320; idx += TPB) sHist[idx] = 0.f;
        __syncthreads();

        const int e = lane >> 2;                          // eighth 0..7
        const int i = bid * 32 + warp * 4 + (lane & 3);   // pair 0..1023
        const int fbase = e * 8;

        const float4* spA = (const float4*)(sp + (2 * i)     * 64 + fbase);
        const float4* spB = (const float4*)(sp + (2 * i + 1) * 64 + fbase);
        const float4* tpA = (const float4*)(tp + (2 * i)     * 64 + fbase);
        const float4* tpB = (const float4*)(tp + (2 * i + 1) * 64 + fbase);

        float sA[OCH], sB[OCH], tA[OCH], tB[OCH];
        #pragma unroll
        for (int k = 0; k < OCH; k++) { sA[k] = sB[k] = tA[k] = tB[k] = 0.f; }

        #pragma unroll
        for (int v = 0; v < 2; v++) {
            float4 a = spA[v], b = spB[v], c = tpA[v], d4 = tpB[v];
            int f = fbase + 4 * v;
            #pragma unroll
            for (int k = 0; k < OCH; k++) {
                float4 w2a = *(const float4*)&sW[k * 128 + f];
                float4 w2b = *(const float4*)&sW[k * 128 + 64 + f];
                float4 w1a = *(const float4*)&sW[OCH * 128 + k * 128 + f];
                float4 w1b = *(const float4*)&sW[OCH * 128 + k * 128 + 64 + f];
                sA[k] += a.x*w2a.x + a.y*w2a.y + a.z*w2a.z + a.w*w2a.w;
                sB[k] += b.x*w2b.x + b.y*w2b.y + b.z*w2b.z + b.w*w2b.w;
                tA[k] += c.x*w1a.x + c.y*w1a.y + c.z*w1a.z + c.w*w1a.w;
                tB[k] += d4.x*w1b.x + d4.y*w1b.y + d4.z*w1b.z + d4.w*w1b.w;
            }
        }
        // combine eighths: xor 4, 8, 16 -> all lanes hold full pair sums
        // (pair identified by lane & 3, replicated 8x across the warp)
        #pragma unroll
        for (int k = 0; k < OCH; k++) {
            #pragma unroll
            for (int o = 4; o <= 16; o <<= 1) {
                sA[k] += __shfl_xor_sync(0xffffffffu, sA[k], o);
                sB[k] += __shfl_xor_sync(0xffffffffu, sB[k], o);
                tA[k] += __shfl_xor_sync(0xffffffffu, tA[k], o);
                tB[k] += __shfl_xor_sync(0xffffffffu, tB[k], o);
            }
        }

        // 2-shfl reduction over the 4 distinct pairs in this warp
        #define WST(j, val) { float r_ = quad_sum(val); \
                              if (lane == 0) sStat[warp * F_NSTAT + (j)] = r_; }
        #pragma unroll
        for (int k = 0; k < OCH; k++) {
            float d = sB[k] - tB[k];
            float ev = sA[k] - tA[k];
            WST(F_DIFF + 4 * k + 0, d);
            WST(F_DIFF + 4 * k + 1, d * d);
            WST(F_DIFF + 4 * k + 2, ev);
            WST(F_DIFF + 4 * k + 3, ev * ev);
        }
        WST(F_DIAG, sB[0] + sA[0]);
        #pragma unroll
        for (int c = 1; c < OCH; c++) {
            WST(F_SXB + (c - 1), sB[c]);
            WST(F_SYA + (c - 1), sA[c]);
            if (c >= 2) {
                WST(F_SXB2 + (c - 2), sB[c] * sB[c]);
                WST(F_SYA2 + (c - 2), sA[c] * sA[c]);
            }
        }
        #undef WST

        // channel-split histograms: group e owns channel c = e+1
        {
            float myA = 0.f, myB = 0.f;
            #pragma unroll
            for (int c = 1; c < OCH; c++) {
                if (e == c - 1) { myA = sA[c]; myB = sB[c]; }
            }
            int v1 = targets[(2 * i)     * 8 + e];
            int v2 = targets[(2 * i + 1) * 8 + e];
            int off = e * 10;
            atomicAdd(&sHist[off + v1],       1.0f);     // cnt1
            atomicAdd(&sHist[160 + off + v1], myA);      // hA
            atomicAdd(&sHist[80 + off + v2],  1.0f);     // cnt2
            atomicAdd(&sHist[240 + off + v2], myB);      // hB
        }
        __syncthreads();

        // block combine -> global partials
        for (int j = tid; j < F_NSTAT; j += TPB) {
            float s = 0.f;
            #pragma unroll
            for (int w = 0; w < 8; w++) s += sStat[w * F_NSTAT + j];
            g_pp[bid][j] = s;
        }
        for (int j = tid; j < 320; j += TPB) g_pp[bid][F_NSTAT + j] = sHist[j];
    } else {
        // ----------------- logits CE + KL: 1 row per warp, no-max softmax --
        const int lb  = bid - POLICY_BLOCKS;          // 0..255
        const int row = lb * 8 + warp;
        const float4* s4 = (const float4*)(slog + row * NCLS);
        const float4* t4 = (const float4*)(tlog + row * NCLS);
        const int label = targets[row * 8];

        float se = 0.f, se4 = 0.f, st = 0.f, slabel = 0.f;
        float svv[4], e4t[4], tvv[4];
        bool act = (lane < 25);
        if (act) {
            float4 sv = s4[lane];
            float4 tv = t4[lane];
            svv[0] = sv.x; svv[1] = sv.y; svv[2] = sv.z; svv[3] = sv.w;
            tvv[0] = tv.x; tvv[1] = tv.y; tvv[2] = tv.z; tvv[3] = tv.w;
            #pragma unroll
            for (int j = 0; j < 4; j++) {
                se  += __expf(svv[j]);
                se4 += __expf(svv[j] * 0.25f);
                e4t[j] = __expf(tvv[j] * 0.25f);
                st  += e4t[j];
                if (4 * lane + j == label) slabel = svv[j];
            }
        } else {
            svv[0]=svv[1]=svv[2]=svv[3]=0.f;
            tvv[0]=tvv[1]=tvv[2]=tvv[3]=0.f;
            e4t[0]=e4t[1]=e4t[2]=e4t[3]=0.f;
        }
        se     = warp_sum(se);
        se4    = warp_sum(se4);
        st     = warp_sum(st);
        slabel = warp_sum(slabel);
        float lse   = __logf(se);
        float lse4  = __logf(se4);
        float logst = __logf(st);
        float ce = lse - slabel;

        float klloc = 0.f;
        if (act) {
            #pragma unroll
            for (int j = 0; j < 4; j++)
                klloc += e4t[j] * (0.25f * (tvv[j] - svv[j]) - logst + lse4);
        }
        float kl = warp_sum(klloc) / st;

        if (lane == 0) { sRed[warp] = ce; sRed[8 + warp] = kl; }
        __syncthreads();
        if (tid == 0) {
            float tc = 0.f, tk = 0.f;
            #pragma unroll
            for (int w = 0; w < 8; w++) { tc += sRed[w]; tk += sRed[8 + w]; }
            g_lp[lb * 2]     = tc;
            g_lp[lb * 2 + 1] = tk;
        }
    }

    // ----------------- last-block-done finalize ---------------------------
    __threadfence();
    if (tid == 0) {
        unsigned t = atomicAdd(&g_ticket, 1u);
        is_last = (t == GRID_BLOCKS - 1) ? 1u : 0u;
    }
    __syncthreads();
    if (!is_last) return;
    if (tid == 0) g_ticket = 0;   // reset for next graph replay
    __threadfence();

    if (tid < OCH) { b1s[tid] = bias1[tid]; b2s[tid] = bias2[tid]; }

    // gather logits partials (256 pairs -> one per thread)
    {
        float vce = g_lp[tid * 2];
        float vkl = g_lp[tid * 2 + 1];
        vce = warp_sum(vce);
        vkl = warp_sum(vkl);
        if (lane == 0) { sRed[warp] = vce; sRed[8 + warp] = vkl; }
    }

    // gather policy partials
    for (int idx = tid; idx < F_SIZE; idx += TPB) {
        float s = 0.f;
        #pragma unroll
        for (int p = 0; p < POLICY_BLOCKS; p++) s += g_pp[p][idx];
        sAcc[idx] = s;
    }
    __syncthreads();

    if (tid == 0) {
        float ce_sum = 0.f, kl_sum = 0.f;
        #pragma unroll
        for (int w = 0; w < 8; w++) { ce_sum += sRed[w]; kl_sum += sRed[8 + w]; }

        const float N = (float)NPAIR;
        const float M = N * N;

        float ce = ce_sum / (float)BATCH;
        float kl = 16.0f * kl_sum / ((float)BATCH * (float)NCLS);

        // policy "kl": weighted means of (s - t)^2 over the pair grid
        float klp = 0.f, pgrid = 0.f;
        for (int k = 0; k < OCH; k++) {
            float db  = b2s[k] - b1s[k];
            float SDr = sAcc[F_DIFF + 4 * k + 0];
            float SD2 = sAcc[F_DIFF + 4 * k + 1];
            float SEr = sAcc[F_DIFF + 4 * k + 2];
            float SE2 = sAcc[F_DIFF + 4 * k + 3];
            float Sd  = SDr + N * db;
            float Sd2 = SD2 + 2.f * db * SDr + N * db * db;
            float grid = N * Sd2 + N * SE2 + 2.f * Sd * SEr;
            if (k == 0)      klp += grid / M;
            else if (k == 1) klp += 0.5f * grid / M;
            else             pgrid += grid;
        }
        klp += 0.001f * pgrid / (7.f * M);

        // policy "ce": identity channel diagonal
        float termI = -(sAcc[F_DIAG] + N * b2s[0]) / M;

        // class channel (c=1): matching-pair sum via histograms
        float sm1 = 0.f;
        for (int v = 0; v < 10; v++) {
            float c1 = sAcc[F_CNT1 + v];
            float c2 = sAcc[F_CNT2 + v];
            float hA = sAcc[F_HA + v];
            float hB = sAcc[F_HB + v];
            sm1 += c1 * hB + c2 * hA + c1 * c2 * b2s[1];
        }
        float termC = -0.5f * sm1 / M;

        // policy channels c=2..8: 0.001 * mean((sP - gP)^2), gP = +-1
        float accP = 0.f;
        for (int c = 2; c < OCH; c++) {
            float b    = b2s[c];
            float SxB  = sAcc[F_SXB  + (c - 1)];
            float SxB2 = sAcc[F_SXB2 + (c - 2)];
            float SyA  = sAcc[F_SYA  + (c - 1)];
            float SyA2 = sAcc[F_SYA2 + (c - 2)];
            float Sx   = SxB + N * b;
            float Sx2  = SxB2 + 2.f * b * SxB + N * b * b;
            float Sw2  = N * Sx2 + N * SyA2 + 2.f * Sx * SyA;
            float sm = 0.f;
            int off = (c - 1) * 10;
            for (int v = 0; v < 10; v++) {
                float c1 = sAcc[F_CNT1 + off + v];
                float c2 = sAcc[F_CNT2 + off + v];
                float hA = sAcc[F_HA + off + v];
                float hB = sAcc[F_HB + off + v];
                sm += c1 * (hB + b * c2) + c2 * hA;
            }
            float Swg = 2.f * sm - N * (Sx + SyA);
            accP += Sw2 - 2.f * Swg + M;
        }
        float termP = 0.001f * accP / (7.f * M);

        out[0] = ce + kl + klp + termI + termC + termP;
    }
}

// ---------------------------------------------------------------------------
extern "C" void kernel_launch(void* const* d_in, const int* in_sizes, int n_in,
                              void* d_out, int out_size) {
    const float* student_logits = (const float*)d_in[0];
    const float* teacher_logits = (const float*)d_in[1];
    const float* student_policy = (const float*)d_in[2];
    const float* teacher_policy = (const float*)d_in[3];
    const float* W1             = (const float*)d_in[4];
    const float* bias1          = (const float*)d_in[5];
    const float* W2             = (const float*)d_in[6];
    const float* bias2          = (const float*)d_in[7];
    const int*   targets        = (const int*)d_in[8];
    float* out = (float*)d_out;

    fused_kernel<<<GRID_BLOCKS, TPB>>>(student_logits, teacher_logits,
                                       student_policy, teacher_policy,
                                       W1, bias1, W2, bias2, targets, out);
}